// round 10
// baseline (speedup 1.0000x reference)
#include <cuda_runtime.h>
#include <cuda_fp16.h>
#include <cstdint>
#include <cstddef>

#define TOT   4096
#define SDIM  1024
#define BATCH 256

// ---------------------------------------------------------------------------
// Device scratch (no cudaMalloc allowed)
// ---------------------------------------------------------------------------
__device__ float g_E[BATCH * SDIM];          // fp32 E activations
__device__ float g_Hf[BATCH * TOT];          // fp32 final state (for logits)
__device__ __half g_Wh[(size_t)TOT * TOT];   // W hi, NATURAL layout [k][n]
__device__ __half g_Wl[(size_t)TOT * TOT];   // W lo, NATURAL layout [k][n]
__device__ __half g_Hh[2][BATCH * TOT];      // state hi (ping-pong)
__device__ __half g_Hl[2][BATCH * TOT];      // state lo (ping-pong)
__device__ float g_outw[1000 * 1024];        // device copy of out_w
__device__ float g_outb[1024];               // device copy of out_b

// ---------------------------------------------------------------------------
// PTX helpers (baseline PTX only: cp.async, ldmatrix, mma.sync)
// ---------------------------------------------------------------------------
__device__ __forceinline__ uint32_t smem_u32(const void* p) {
    uint32_t a;
    asm("{ .reg .u64 t; cvta.to.shared.u64 t, %1; cvt.u32.u64 %0, t; }"
        : "=r"(a) : "l"(p));
    return a;
}
__device__ __forceinline__ void cpa16(uint32_t dst, const void* src) {
    asm volatile("cp.async.cg.shared.global [%0], [%1], 16;"
                 :: "r"(dst), "l"(src));
}
#define CP_COMMIT() asm volatile("cp.async.commit_group;" ::: "memory")
#define CP_WAIT(n)  asm volatile("cp.async.wait_group %0;" :: "n"(n) : "memory")

__device__ __forceinline__ void ldsm4(uint32_t* r, uint32_t addr) {
    asm volatile("ldmatrix.sync.aligned.m8n8.x4.shared.b16 {%0,%1,%2,%3}, [%4];"
                 : "=r"(r[0]), "=r"(r[1]), "=r"(r[2]), "=r"(r[3]) : "r"(addr));
}
__device__ __forceinline__ void ldsm4t(uint32_t* r, uint32_t addr) {
    asm volatile("ldmatrix.sync.aligned.m8n8.x4.trans.shared.b16 {%0,%1,%2,%3}, [%4];"
                 : "=r"(r[0]), "=r"(r[1]), "=r"(r[2]), "=r"(r[3]) : "r"(addr));
}
__device__ __forceinline__ void mma16816(float* d, const uint32_t* a,
                                         const uint32_t* b) {
    asm volatile(
        "mma.sync.aligned.m16n8k16.row.col.f32.f16.f16.f32 "
        "{%0,%1,%2,%3}, {%4,%5,%6,%7}, {%8,%9}, {%0,%1,%2,%3};\n"
        : "+f"(d[0]), "+f"(d[1]), "+f"(d[2]), "+f"(d[3])
        : "r"(a[0]), "r"(a[1]), "r"(a[2]), "r"(a[3]), "r"(b[0]), "r"(b[1]));
}

__device__ __forceinline__ unsigned long long pk2(float lo, float hi) {
    unsigned long long r;
    asm("mov.b64 %0, {%1, %2};" : "=l"(r) : "f"(lo), "f"(hi));
    return r;
}
__device__ __forceinline__ unsigned long long fma2(unsigned long long a,
                                                   unsigned long long b,
                                                   unsigned long long c) {
    unsigned long long d;
    asm("fma.rn.f32x2 %0, %1, %2, %3;" : "=l"(d) : "l"(a), "l"(b), "l"(c));
    return d;
}
__device__ __forceinline__ float2 up2(unsigned long long v) {
    float lo, hi;
    asm("mov.b64 {%0, %1}, %2;" : "=f"(lo), "=f"(hi) : "l"(v));
    return make_float2(lo, hi);
}

// ---------------------------------------------------------------------------
// Step GEMM (unchanged from R8 — proven): 64x64 tile, 3-stage cp.async,
// A non-trans ldmatrix, B natural [k][n] via ldmatrix.x4.trans.
// ---------------------------------------------------------------------------
#define ST_A   8192
#define STAGE  16384
#define SMEM_STEP (3 * STAGE)

__global__ __launch_bounds__(128, 2)
void step_hmma(const __half* __restrict__ Ah,
               const __half* __restrict__ Al,
               const __half* __restrict__ Bh,
               const __half* __restrict__ Bl,
               const float* __restrict__ E,
               __half* __restrict__ Oh,
               __half* __restrict__ Ol,
               float* __restrict__ Of,
               int K, int addE, int writeF)
{
    extern __shared__ char dsm[];
    const uint32_t sb = smem_u32(dsm);
    const int tid  = threadIdx.x;
    const int lane = tid & 31;
    const int wid  = tid >> 5;
    const int wm   = wid & 1;
    const int wn   = wid >> 1;
    const int row0 = blockIdx.y * 64;
    const int n0   = blockIdx.x * 64;

    const int kPer  = K >> 6;
    const int nIter = 3 * kPer;

    const int laneRowA = (lane & 7) + ((lane >> 3) & 1) * 8;
    const int kTileA   = lane >> 4;
    const int x7a      = laneRowA & 7;

    const int mB = lane >> 3;
    const int rB = lane & 7;
    const int khB = mB & 1, tpB = mB >> 1;

    auto issue = [&](int it, int buf) {
        const int p  = it / kPer;
        const int kc = it - p * kPer;
        const __half* As = (p == 2) ? Al : Ah;
        const __half* Bs = (p == 1) ? Bl : Bh;
        const __half* Ag = As + (size_t)row0 * TOT + kc * 64;
        const __half* Bg = Bs + (size_t)(kc * 64) * TOT + n0;
        const uint32_t sA = sb + buf * STAGE;
        const uint32_t sB = sA + ST_A;
#pragma unroll
        for (int i = 0; i < 4; i++) {
            const int idx = tid + 128 * i;
            const int r = idx >> 3, g = idx & 7;
            const uint32_t off = r * 128 + ((g ^ (r & 7)) << 4);
            cpa16(sA + off, Ag + (size_t)r * TOT + g * 8);
            cpa16(sB + off, Bg + (size_t)r * TOT + g * 8);
        }
    };

    float acc[2][4][4];
#pragma unroll
    for (int mt = 0; mt < 2; mt++)
#pragma unroll
        for (int nt = 0; nt < 4; nt++)
#pragma unroll
            for (int i = 0; i < 4; i++) acc[mt][nt][i] = 0.f;

    issue(0, 0); CP_COMMIT();
    issue(1, 1); CP_COMMIT();

    for (int it = 0; it < nIter; it++) {
        CP_WAIT(1);
        __syncthreads();

        if (it + 2 < nIter) issue(it + 2, (it + 2) % 3);
        CP_COMMIT();

        const uint32_t sA = sb + (it % 3) * STAGE;
        const uint32_t sB = sA + ST_A;
#pragma unroll
        for (int ks = 0; ks < 4; ks++) {
            uint32_t aF[2][4], bF[4][2];
#pragma unroll
            for (int mt = 0; mt < 2; mt++) {
                const int row = wm * 32 + mt * 16 + laneRowA;
                ldsm4(aF[mt], sA + row * 128 + (((2 * ks + kTileA) ^ x7a) << 4));
            }
            {
                const int krow = ks * 16 + khB * 8 + rB;
                const int x7k  = krow & 7;
#pragma unroll
                for (int c = 0; c < 2; c++) {
                    const int g = wn * 4 + c * 2 + tpB;
                    uint32_t q[4];
                    ldsm4t(q, sB + krow * 128 + ((g ^ x7k) << 4));
                    bF[c * 2 + 0][0] = q[0]; bF[c * 2 + 0][1] = q[1];
                    bF[c * 2 + 1][0] = q[2]; bF[c * 2 + 1][1] = q[3];
                }
            }
#pragma unroll
            for (int mt = 0; mt < 2; mt++)
#pragma unroll
                for (int nt = 0; nt < 4; nt++)
                    mma16816(acc[mt][nt], aF[mt], bF[nt]);
        }
    }

    const int gr = lane >> 2, tidg = lane & 3;
    const bool doE = (addE != 0) && (n0 < SDIM);
#pragma unroll
    for (int mt = 0; mt < 2; mt++) {
#pragma unroll
        for (int rh = 0; rh < 2; rh++) {
            const int grow = row0 + wm * 32 + mt * 16 + gr + 8 * rh;
#pragma unroll
            for (int nt = 0; nt < 4; nt++) {
                const int col = n0 + wn * 32 + nt * 8 + tidg * 2;
                float v0 = acc[mt][nt][2 * rh];
                float v1 = acc[mt][nt][2 * rh + 1];
                if (doE) {
                    const float* ep = E + (size_t)grow * SDIM + col;
                    v0 += ep[0]; v1 += ep[1];
                }
                v0 = fmaxf(v0, 0.f); v1 = fmaxf(v1, 0.f);
                __half h0 = __float2half(v0);
                __half h1 = __float2half(v1);
                __half l0 = __float2half(v0 - __half2float(h0));
                __half l1 = __float2half(v1 - __half2float(h1));
                const size_t o = (size_t)grow * TOT + col;
                *(__half2*)(Oh + o) = __halves2half2(h0, h1);
                *(__half2*)(Ol + o) = __halves2half2(l0, l1);
                if (writeF) *(float2*)(Of + o) = make_float2(v0, v1);
            }
        }
    }
}

// ---------------------------------------------------------------------------
// Fused prep mega-kernel (single launch; sections co-resident on the SM pool):
//   blocks [0, 64)      : E = x@in_w^T + in_b  AND  H0 S-block = split(relu(E))
//   blocks [64, 4160)   : W -> fp16 hi/lo split (streaming)
//   blocks [4160, 5160) : prefetch out_w/out_b into device scratch
// Step 1 reads only H cols [0,1024) (K=1024), so the I/O block of H0 never
// needs initialization.
// ---------------------------------------------------------------------------
__global__ __launch_bounds__(256) void prep(
    const float* __restrict__ x,
    const float* __restrict__ in_w,
    const float* __restrict__ in_b,
    const float* __restrict__ W,
    const float* __restrict__ out_w,
    const float* __restrict__ out_b,
    float* __restrict__ E,
    __half* __restrict__ Hh,
    __half* __restrict__ Hl,
    __half* __restrict__ Wh,
    __half* __restrict__ Wl,
    float* __restrict__ dow,
    float* __restrict__ dob)
{
    const int bx  = blockIdx.x;
    const int tid = threadIdx.x;

    if (bx >= 64) {
        if (bx < 4160) {
            // ---- splitW section ----
            const size_t base = (size_t)(bx - 64) * 1024 + tid;   // float4 units
            float4 v[4];
#pragma unroll
            for (int k = 0; k < 4; k++)
                v[k] = ((const float4*)W)[base + (size_t)k * 256];
#pragma unroll
            for (int k = 0; k < 4; k++) {
                float a[4] = {v[k].x, v[k].y, v[k].z, v[k].w};
                __align__(8) __half h[4];
                __align__(8) __half l[4];
#pragma unroll
                for (int j = 0; j < 4; j++) {
                    __half hi = __float2half(a[j]);
                    h[j] = hi;
                    l[j] = __float2half(a[j] - __half2float(hi));
                }
                const size_t o = (base + (size_t)k * 256) * 4;
                *(uint2*)(Wh + o) = *(uint2*)h;
                *(uint2*)(Wl + o) = *(uint2*)l;
            }
        } else {
            // ---- prefetch out_w / out_b section ----
            const int i = (bx - 4160) * 256 + tid;
            ((float4*)dow)[i] = ((const float4*)out_w)[i];
            if (bx == 4160 && tid < 250)
                ((float4*)dob)[tid] = ((const float4*)out_b)[tid];
        }
        return;
    }

    // ---- E-GEMM section: C[256,1024] = x[256,2048] @ in_w[1024,2048]^T + b ----
    __shared__ float As[2][16][68];
    __shared__ float Bs[2][16][68];

    const int row0 = (bx >> 4) * 64;
    const int col0 = (bx & 15) * 64;

    const int am = tid >> 2;
    const int ak = (tid & 3) << 2;
    const float* Ap = x    + (size_t)(row0 + am) * 2048 + ak;
    const float* Bp = in_w + (size_t)(col0 + am) * 2048 + ak;

    const int tx = tid & 15;
    const int ty = tid >> 4;

    unsigned long long acc[4][2];
#pragma unroll
    for (int i = 0; i < 4; i++) { acc[i][0] = 0ull; acc[i][1] = 0ull; }

    {
        float4 av = *(const float4*)Ap;
        float4 bv = *(const float4*)Bp;
        As[0][ak + 0][am] = av.x; As[0][ak + 1][am] = av.y;
        As[0][ak + 2][am] = av.z; As[0][ak + 3][am] = av.w;
        Bs[0][ak + 0][am] = bv.x; Bs[0][ak + 1][am] = bv.y;
        Bs[0][ak + 2][am] = bv.z; Bs[0][ak + 3][am] = bv.w;
    }
    __syncthreads();

    for (int s = 0; s < 128; s++) {
        const int cur = s & 1;
        float4 av, bv;
        const bool pf = (s + 1 < 128);
        if (pf) {
            av = *(const float4*)(Ap + (s + 1) * 16);
            bv = *(const float4*)(Bp + (s + 1) * 16);
        }
#pragma unroll
        for (int k = 0; k < 16; k++) {
            float4 a4 = *(const float4*)&As[cur][k][ty << 2];
            ulonglong2 bb = *(const ulonglong2*)&Bs[cur][k][tx << 2];
            unsigned long long b0 = bb.x, b1 = bb.y;
            unsigned long long p0 = pk2(a4.x, a4.x);
            unsigned long long p1 = pk2(a4.y, a4.y);
            unsigned long long p2 = pk2(a4.z, a4.z);
            unsigned long long p3 = pk2(a4.w, a4.w);
            acc[0][0] = fma2(p0, b0, acc[0][0]); acc[0][1] = fma2(p0, b1, acc[0][1]);
            acc[1][0] = fma2(p1, b0, acc[1][0]); acc[1][1] = fma2(p1, b1, acc[1][1]);
            acc[2][0] = fma2(p2, b0, acc[2][0]); acc[2][1] = fma2(p2, b1, acc[2][1]);
            acc[3][0] = fma2(p3, b0, acc[3][0]); acc[3][1] = fma2(p3, b1, acc[3][1]);
        }
        if (pf) {
            const int nx = cur ^ 1;
            As[nx][ak + 0][am] = av.x; As[nx][ak + 1][am] = av.y;
            As[nx][ak + 2][am] = av.z; As[nx][ak + 3][am] = av.w;
            Bs[nx][ak + 0][am] = bv.x; Bs[nx][ak + 1][am] = bv.y;
            Bs[nx][ak + 2][am] = bv.z; Bs[nx][ak + 3][am] = bv.w;
        }
        __syncthreads();
    }

    const int crow = row0 + (ty << 2);
    const int ccol = col0 + (tx << 2);
#pragma unroll
    for (int m = 0; m < 4; m++) {
#pragma unroll
        for (int j = 0; j < 2; j++) {
            float2 f = up2(acc[m][j]);
            const int c = ccol + 2 * j;
            const int grow = crow + m;
            float v0 = f.x + in_b[c];
            float v1 = f.y + in_b[c + 1];
            // E (needed at t=5 gate)
            *(float2*)(E + (size_t)grow * SDIM + c) = make_float2(v0, v1);
            // fused t=0 state: H0 S-block = split(relu(E))
            float r0 = fmaxf(v0, 0.f), r1 = fmaxf(v1, 0.f);
            __half h0 = __float2half(r0), h1 = __float2half(r1);
            __half l0 = __float2half(r0 - __half2float(h0));
            __half l1 = __float2half(r1 - __half2float(h1));
            const size_t o = (size_t)grow * TOT + c;
            *(__half2*)(Hh + o) = __halves2half2(h0, h1);
            *(__half2*)(Hl + o) = __halves2half2(l0, l1);
        }
    }
}

// ---------------------------------------------------------------------------
// SIMT fp32x2 GEMM (proven): logits = Hf_O @ out_w^T + out_b
// ---------------------------------------------------------------------------
__global__ __launch_bounds__(256, 1) void gemm_tn_bias(
    const float* __restrict__ A, int lda,
    const float* __restrict__ B, int ldb,
    const float* __restrict__ bias,
    float* __restrict__ C, int ldc,
    int N, int K)
{
    __shared__ float As[2][16][68];
    __shared__ float Bs[2][16][68];

    const int tid  = threadIdx.x;
    const int row0 = blockIdx.y * 64;
    const int col0 = blockIdx.x * 64;

    const int am = tid >> 2;
    const int ak = (tid & 3) << 2;
    const float* Ap = A + (size_t)(row0 + am) * lda + ak;
    const bool bval = (col0 + am) < N;
    const float* Bp = B + (size_t)(col0 + am) * ldb + ak;

    const int tx = tid & 15;
    const int ty = tid >> 4;

    unsigned long long acc[4][2];
#pragma unroll
    for (int i = 0; i < 4; i++) { acc[i][0] = 0ull; acc[i][1] = 0ull; }

    const int nst = K >> 4;

    {
        float4 av = *(const float4*)Ap;
        float4 bv = bval ? *(const float4*)Bp : make_float4(0.f, 0.f, 0.f, 0.f);
        As[0][ak + 0][am] = av.x; As[0][ak + 1][am] = av.y;
        As[0][ak + 2][am] = av.z; As[0][ak + 3][am] = av.w;
        Bs[0][ak + 0][am] = bv.x; Bs[0][ak + 1][am] = bv.y;
        Bs[0][ak + 2][am] = bv.z; Bs[0][ak + 3][am] = bv.w;
    }
    __syncthreads();

    for (int s = 0; s < nst; s++) {
        const int cur = s & 1;
        float4 av, bv;
        const bool pf = (s + 1 < nst);
        if (pf) {
            av = *(const float4*)(Ap + (s + 1) * 16);
            bv = bval ? *(const float4*)(Bp + (s + 1) * 16)
                      : make_float4(0.f, 0.f, 0.f, 0.f);
        }
#pragma unroll
        for (int k = 0; k < 16; k++) {
            float4 a4 = *(const float4*)&As[cur][k][ty << 2];
            ulonglong2 bb = *(const ulonglong2*)&Bs[cur][k][tx << 2];
            unsigned long long b0 = bb.x, b1 = bb.y;
            unsigned long long p0 = pk2(a4.x, a4.x);
            unsigned long long p1 = pk2(a4.y, a4.y);
            unsigned long long p2 = pk2(a4.z, a4.z);
            unsigned long long p3 = pk2(a4.w, a4.w);
            acc[0][0] = fma2(p0, b0, acc[0][0]); acc[0][1] = fma2(p0, b1, acc[0][1]);
            acc[1][0] = fma2(p1, b0, acc[1][0]); acc[1][1] = fma2(p1, b1, acc[1][1]);
            acc[2][0] = fma2(p2, b0, acc[2][0]); acc[2][1] = fma2(p2, b1, acc[2][1]);
            acc[3][0] = fma2(p3, b0, acc[3][0]); acc[3][1] = fma2(p3, b1, acc[3][1]);
        }
        if (pf) {
            const int nx = cur ^ 1;
            As[nx][ak + 0][am] = av.x; As[nx][ak + 1][am] = av.y;
            As[nx][ak + 2][am] = av.z; As[nx][ak + 3][am] = av.w;
            Bs[nx][ak + 0][am] = bv.x; Bs[nx][ak + 1][am] = bv.y;
            Bs[nx][ak + 2][am] = bv.z; Bs[nx][ak + 3][am] = bv.w;
        }
        __syncthreads();
    }

    const int crow = row0 + (ty << 2);
    const int ccol = col0 + (tx << 2);
#pragma unroll
    for (int m = 0; m < 4; m++) {
#pragma unroll
        for (int j = 0; j < 2; j++) {
            float2 f = up2(acc[m][j]);
            int c = ccol + 2 * j;
            if (c < N)     C[(size_t)(crow + m) * ldc + c]     = f.x + bias[c];
            if (c + 1 < N) C[(size_t)(crow + m) * ldc + c + 1] = f.y + bias[c + 1];
        }
    }
}

// ---------------------------------------------------------------------------
// Launch sequence (graph-capturable: single stream, kernels only, no streams
// or events — avoids the R9 teardown leak entirely)
// ---------------------------------------------------------------------------
extern "C" void kernel_launch(void* const* d_in, const int* in_sizes, int n_in,
                              void* d_out, int out_size)
{
    const float* x     = (const float*)d_in[0];
    const float* W     = (const float*)d_in[1];
    const float* in_w  = (const float*)d_in[2];
    const float* in_b  = (const float*)d_in[3];
    const float* out_w = (const float*)d_in[4];
    const float* out_b = (const float*)d_in[5];
    float* out = (float*)d_out;

    float *E, *Hf, *dow, *dob;
    __half *Wh, *Wl, *Hh, *Hl;
    cudaGetSymbolAddress((void**)&E,   g_E);
    cudaGetSymbolAddress((void**)&Hf,  g_Hf);
    cudaGetSymbolAddress((void**)&Wh,  g_Wh);
    cudaGetSymbolAddress((void**)&Wl,  g_Wl);
    cudaGetSymbolAddress((void**)&Hh,  g_Hh);
    cudaGetSymbolAddress((void**)&Hl,  g_Hl);
    cudaGetSymbolAddress((void**)&dow, g_outw);
    cudaGetSymbolAddress((void**)&dob, g_outb);

    cudaFuncSetAttribute(step_hmma, cudaFuncAttributeMaxDynamicSharedMemorySize,
                         SMEM_STEP);

    // fused prep: E-GEMM + t0 state + W split + out_w prefetch, one wave
    prep<<<5160, 256>>>(x, in_w, in_b, W, out_w, out_b,
                        E, Hh, Hl, Wh, Wl, dow, dob);

    // t = 1..9: H_next = relu(H @ W + g_t * [E,0,0]); t=1 has K=1024
    int cur = 0;
    for (int t = 1; t < 10; t++) {
        int K      = (t == 1) ? SDIM : TOT;
        int addE   = (t % 5 == 0) ? 1 : 0;
        int writeF = (t == 9) ? 1 : 0;
        __half* Ahp = Hh + (size_t)cur * BATCH * TOT;
        __half* Alp = Hl + (size_t)cur * BATCH * TOT;
        __half* Ohp = Hh + (size_t)(1 - cur) * BATCH * TOT;
        __half* Olp = Hl + (size_t)(1 - cur) * BATCH * TOT;
        step_hmma<<<dim3(64, 4), 128, SMEM_STEP>>>(Ahp, Alp, Wh, Wl, E,
                                                   Ohp, Olp, Hf, K, addE, writeF);
        cur = 1 - cur;
    }

    // logits = O_state @ out_w^T + out_b  (device copies; O = cols [3072,4096))
    gemm_tn_bias<<<dim3(16, 4), 256>>>(Hf + 3072, TOT, dow, 1024, dob,
                                       out, 1000, 1000, 1024);
}

// round 12
// speedup vs baseline: 1.7981x; 1.7981x over previous
#include <cuda_runtime.h>
#include <cuda_fp16.h>
#include <cstdint>
#include <cstddef>

#define TOT   4096
#define SDIM  1024
#define BATCH 256

// ---------------------------------------------------------------------------
// Device scratch (no cudaMalloc allowed)
// ---------------------------------------------------------------------------
__device__ float g_E[BATCH * SDIM];          // fp32 E activations
__device__ float g_Hf[BATCH * TOT];          // fp32 final state (for logits)
__device__ __half g_Wh[(size_t)TOT * TOT];   // W hi, NATURAL layout [k][n]
__device__ __half g_Wl[(size_t)TOT * TOT];   // W lo, NATURAL layout [k][n]
__device__ __half g_Hh[2][BATCH * TOT];      // state hi (ping-pong)
__device__ __half g_Hl[2][BATCH * TOT];      // state lo (ping-pong)

// ---------------------------------------------------------------------------
// PTX helpers (baseline PTX only: cp.async, ldmatrix, mma.sync)
// ---------------------------------------------------------------------------
__device__ __forceinline__ uint32_t smem_u32(const void* p) {
    uint32_t a;
    asm("{ .reg .u64 t; cvta.to.shared.u64 t, %1; cvt.u32.u64 %0, t; }"
        : "=r"(a) : "l"(p));
    return a;
}
__device__ __forceinline__ void cpa16(uint32_t dst, const void* src) {
    asm volatile("cp.async.cg.shared.global [%0], [%1], 16;"
                 :: "r"(dst), "l"(src));
}
#define CP_COMMIT() asm volatile("cp.async.commit_group;" ::: "memory")
#define CP_WAIT(n)  asm volatile("cp.async.wait_group %0;" :: "n"(n) : "memory")

__device__ __forceinline__ void ldsm4(uint32_t* r, uint32_t addr) {
    asm volatile("ldmatrix.sync.aligned.m8n8.x4.shared.b16 {%0,%1,%2,%3}, [%4];"
                 : "=r"(r[0]), "=r"(r[1]), "=r"(r[2]), "=r"(r[3]) : "r"(addr));
}
__device__ __forceinline__ void ldsm4t(uint32_t* r, uint32_t addr) {
    asm volatile("ldmatrix.sync.aligned.m8n8.x4.trans.shared.b16 {%0,%1,%2,%3}, [%4];"
                 : "=r"(r[0]), "=r"(r[1]), "=r"(r[2]), "=r"(r[3]) : "r"(addr));
}
__device__ __forceinline__ void mma16816(float* d, const uint32_t* a,
                                         const uint32_t* b) {
    asm volatile(
        "mma.sync.aligned.m16n8k16.row.col.f32.f16.f16.f32 "
        "{%0,%1,%2,%3}, {%4,%5,%6,%7}, {%8,%9}, {%0,%1,%2,%3};\n"
        : "+f"(d[0]), "+f"(d[1]), "+f"(d[2]), "+f"(d[3])
        : "r"(a[0]), "r"(a[1]), "r"(a[2]), "r"(a[3]), "r"(b[0]), "r"(b[1]));
}

// ---------------------------------------------------------------------------
// Step GEMM, merged-product version:
//   C[256,4096] = relu( Ah@Wh + Al@Wh + Ah@Wl  (+ gate*E) )
// ONE K sweep; per 64-wide K chunk the stage holds 4 subtiles
// (Ah, Al, Bh, Bl) and computes all three products -> Wh read ONCE.
// CTA: 128 threads (2m x 2n warps), tile 64x64, 3-stage ring (32KB/stage).
// Grid (64, 4) = 256 CTAs. Proven R8 swizzle + ldmatrix geometry.
// ---------------------------------------------------------------------------
#define SUB    8192                  // one 64-row x 128B subtile
#define STAGE  32768                 // Ah + Al + Bh + Bl
#define SMEM_STEP (3 * STAGE)        // 98304

__global__ __launch_bounds__(128, 2)
void step_hmma(const __half* __restrict__ Ah,
               const __half* __restrict__ Al,
               const __half* __restrict__ Bh,   // natural [k][n]
               const __half* __restrict__ Bl,   // natural [k][n]
               const float* __restrict__ E,
               __half* __restrict__ Oh,
               __half* __restrict__ Ol,
               float* __restrict__ Of,
               int K, int addE, int writeF)
{
    extern __shared__ char dsm[];
    const uint32_t sb = smem_u32(dsm);
    const int tid  = threadIdx.x;
    const int lane = tid & 31;
    const int wid  = tid >> 5;
    const int wm   = wid & 1;
    const int wn   = wid >> 1;
    const int row0 = blockIdx.y * 64;
    const int n0   = blockIdx.x * 64;

    const int nIter = K >> 6;            // one sweep, 64-wide chunks

    // A ldmatrix geometry (non-trans, proven in R8)
    const int laneRowA = (lane & 7) + ((lane >> 3) & 1) * 8;
    const int kTileA   = lane >> 4;
    const int x7a      = laneRowA & 7;

    // B ldmatrix.trans geometry (proven in R8)
    const int mB = lane >> 3;
    const int rB = lane & 7;
    const int khB = mB & 1, tpB = mB >> 1;

    auto issue = [&](int kc, int buf) {
        const __half* Agh = Ah + (size_t)row0 * TOT + kc * 64;
        const __half* Agl = Al + (size_t)row0 * TOT + kc * 64;
        const __half* Bgh = Bh + (size_t)(kc * 64) * TOT + n0;
        const __half* Bgl = Bl + (size_t)(kc * 64) * TOT + n0;
        const uint32_t st = sb + buf * STAGE;
#pragma unroll
        for (int i = 0; i < 4; i++) {
            const int idx = tid + 128 * i;
            const int r = idx >> 3, g = idx & 7;
            const uint32_t off = r * 128 + ((g ^ (r & 7)) << 4);
            const size_t go = (size_t)r * TOT + g * 8;
            cpa16(st + off,           Agh + go);
            cpa16(st + SUB + off,     Agl + go);
            cpa16(st + 2 * SUB + off, Bgh + go);
            cpa16(st + 3 * SUB + off, Bgl + go);
        }
    };

    float acc[2][4][4];
#pragma unroll
    for (int mt = 0; mt < 2; mt++)
#pragma unroll
        for (int nt = 0; nt < 4; nt++)
#pragma unroll
            for (int i = 0; i < 4; i++) acc[mt][nt][i] = 0.f;

    issue(0, 0); CP_COMMIT();
    issue(1, 1); CP_COMMIT();

    for (int it = 0; it < nIter; it++) {
        CP_WAIT(1);
        __syncthreads();

        if (it + 2 < nIter) issue(it + 2, (it + 2) % 3);
        CP_COMMIT();

        const uint32_t st  = sb + (it % 3) * STAGE;
        const uint32_t sAh = st;
        const uint32_t sAl = st + SUB;
        const uint32_t sBh = st + 2 * SUB;
        const uint32_t sBl = st + 3 * SUB;
#pragma unroll
        for (int ks = 0; ks < 4; ks++) {
            uint32_t aH[2][4], aL[2][4], bH[4][2], bL[4][2];
#pragma unroll
            for (int mt = 0; mt < 2; mt++) {
                const int row = wm * 32 + mt * 16 + laneRowA;
                const uint32_t ro = row * 128 + (((2 * ks + kTileA) ^ x7a) << 4);
                ldsm4(aH[mt], sAh + ro);
                ldsm4(aL[mt], sAl + ro);
            }
            {
                const int krow = ks * 16 + khB * 8 + rB;
                const int x7k  = krow & 7;
#pragma unroll
                for (int c = 0; c < 2; c++) {
                    const int g = wn * 4 + c * 2 + tpB;
                    const uint32_t ro = krow * 128 + ((g ^ x7k) << 4);
                    uint32_t q[4];
                    ldsm4t(q, sBh + ro);
                    bH[c * 2 + 0][0] = q[0]; bH[c * 2 + 0][1] = q[1];
                    bH[c * 2 + 1][0] = q[2]; bH[c * 2 + 1][1] = q[3];
                    ldsm4t(q, sBl + ro);
                    bL[c * 2 + 0][0] = q[0]; bL[c * 2 + 0][1] = q[1];
                    bL[c * 2 + 1][0] = q[2]; bL[c * 2 + 1][1] = q[3];
                }
            }
#pragma unroll
            for (int mt = 0; mt < 2; mt++)
#pragma unroll
                for (int nt = 0; nt < 4; nt++) {
                    mma16816(acc[mt][nt], aH[mt], bH[nt]);   // Ah*Wh
                    mma16816(acc[mt][nt], aL[mt], bH[nt]);   // Al*Wh
                    mma16816(acc[mt][nt], aH[mt], bL[nt]);   // Ah*Wl
                }
        }
    }

    // ---- fused epilogue: +gate*E, relu, fp16 hi/lo split, optional fp32 ----
    const int gr = lane >> 2, tidg = lane & 3;
    const bool doE = (addE != 0) && (n0 < SDIM);
#pragma unroll
    for (int mt = 0; mt < 2; mt++) {
#pragma unroll
        for (int rh = 0; rh < 2; rh++) {
            const int grow = row0 + wm * 32 + mt * 16 + gr + 8 * rh;
#pragma unroll
            for (int nt = 0; nt < 4; nt++) {
                const int col = n0 + wn * 32 + nt * 8 + tidg * 2;
                float v0 = acc[mt][nt][2 * rh];
                float v1 = acc[mt][nt][2 * rh + 1];
                if (doE) {
                    const float* ep = E + (size_t)grow * SDIM + col;
                    v0 += ep[0]; v1 += ep[1];
                }
                v0 = fmaxf(v0, 0.f); v1 = fmaxf(v1, 0.f);
                __half h0 = __float2half(v0);
                __half h1 = __float2half(v1);
                __half l0 = __float2half(v0 - __half2float(h0));
                __half l1 = __float2half(v1 - __half2float(h1));
                const size_t o = (size_t)grow * TOT + col;
                *(__half2*)(Oh + o) = __halves2half2(h0, h1);
                *(__half2*)(Ol + o) = __halves2half2(l0, l1);
                if (writeF) *(float2*)(Of + o) = make_float2(v0, v1);
            }
        }
    }
}

// ---------------------------------------------------------------------------
// W -> fp16 hi/lo split, deep-MLP streaming (exactly as R8)
// ---------------------------------------------------------------------------
__global__ __launch_bounds__(256) void splitW(const float* __restrict__ W,
                                              __half* __restrict__ Wh,
                                              __half* __restrict__ Wl)
{
    const size_t base = (size_t)blockIdx.x * 1024 + threadIdx.x;  // float4 units
    float4 v[4];
#pragma unroll
    for (int k = 0; k < 4; k++)
        v[k] = ((const float4*)W)[base + (size_t)k * 256];
#pragma unroll
    for (int k = 0; k < 4; k++) {
        float a[4] = {v[k].x, v[k].y, v[k].z, v[k].w};
        __align__(8) __half h[4];
        __align__(8) __half l[4];
#pragma unroll
        for (int j = 0; j < 4; j++) {
            __half hi = __float2half(a[j]);
            h[j] = hi;
            l[j] = __float2half(a[j] - __half2float(hi));
        }
        const size_t o = (base + (size_t)k * 256) * 4;
        *(uint2*)(Wh + o) = *(uint2*)h;
        *(uint2*)(Wl + o) = *(uint2*)l;
    }
}

// ---------------------------------------------------------------------------
// t = 0:  H = [relu(E), 0, 0]  -> fp16 hi/lo  (exactly as R8)
// ---------------------------------------------------------------------------
__global__ void init_state(__half* __restrict__ Oh, __half* __restrict__ Ol)
{
    int i = blockIdx.x * blockDim.x + threadIdx.x;
    int row = i >> 12, col = i & (TOT - 1);
    float v = 0.f;
    if (col < SDIM) v = fmaxf(g_E[row * SDIM + col], 0.f);
    __half hi = __float2half(v);
    __half lo = __float2half(v - __half2float(hi));
    Oh[i] = hi; Ol[i] = lo;
}

// ---------------------------------------------------------------------------
// SIMT fp32x2 GEMM (proven): C[M,N] = A[M,K] @ B[N,K]^T + bias
// ---------------------------------------------------------------------------
__device__ __forceinline__ unsigned long long pk2(float lo, float hi) {
    unsigned long long r;
    asm("mov.b64 %0, {%1, %2};" : "=l"(r) : "f"(lo), "f"(hi));
    return r;
}
__device__ __forceinline__ unsigned long long fma2(unsigned long long a,
                                                   unsigned long long b,
                                                   unsigned long long c) {
    unsigned long long d;
    asm("fma.rn.f32x2 %0, %1, %2, %3;" : "=l"(d) : "l"(a), "l"(b), "l"(c));
    return d;
}
__device__ __forceinline__ float2 up2(unsigned long long v) {
    float lo, hi;
    asm("mov.b64 {%0, %1}, %2;" : "=f"(lo), "=f"(hi) : "l"(v));
    return make_float2(lo, hi);
}

__global__ __launch_bounds__(256, 1) void gemm_tn_bias(
    const float* __restrict__ A, int lda,
    const float* __restrict__ B, int ldb,
    const float* __restrict__ bias,
    float* __restrict__ C, int ldc,
    int N, int K)
{
    __shared__ float As[2][16][68];
    __shared__ float Bs[2][16][68];

    const int tid  = threadIdx.x;
    const int row0 = blockIdx.y * 64;
    const int col0 = blockIdx.x * 64;

    const int am = tid >> 2;
    const int ak = (tid & 3) << 2;
    const float* Ap = A + (size_t)(row0 + am) * lda + ak;
    const bool bval = (col0 + am) < N;
    const float* Bp = B + (size_t)(col0 + am) * ldb + ak;

    const int tx = tid & 15;
    const int ty = tid >> 4;

    unsigned long long acc[4][2];
#pragma unroll
    for (int i = 0; i < 4; i++) { acc[i][0] = 0ull; acc[i][1] = 0ull; }

    const int nst = K >> 4;

    {
        float4 av = *(const float4*)Ap;
        float4 bv = bval ? *(const float4*)Bp : make_float4(0.f, 0.f, 0.f, 0.f);
        As[0][ak + 0][am] = av.x; As[0][ak + 1][am] = av.y;
        As[0][ak + 2][am] = av.z; As[0][ak + 3][am] = av.w;
        Bs[0][ak + 0][am] = bv.x; Bs[0][ak + 1][am] = bv.y;
        Bs[0][ak + 2][am] = bv.z; Bs[0][ak + 3][am] = bv.w;
    }
    __syncthreads();

    for (int s = 0; s < nst; s++) {
        const int cur = s & 1;
        float4 av, bv;
        const bool pf = (s + 1 < nst);
        if (pf) {
            av = *(const float4*)(Ap + (s + 1) * 16);
            bv = bval ? *(const float4*)(Bp + (s + 1) * 16)
                      : make_float4(0.f, 0.f, 0.f, 0.f);
        }
#pragma unroll
        for (int k = 0; k < 16; k++) {
            float4 a4 = *(const float4*)&As[cur][k][ty << 2];
            ulonglong2 bb = *(const ulonglong2*)&Bs[cur][k][tx << 2];
            unsigned long long b0 = bb.x, b1 = bb.y;
            unsigned long long p0 = pk2(a4.x, a4.x);
            unsigned long long p1 = pk2(a4.y, a4.y);
            unsigned long long p2 = pk2(a4.z, a4.z);
            unsigned long long p3 = pk2(a4.w, a4.w);
            acc[0][0] = fma2(p0, b0, acc[0][0]); acc[0][1] = fma2(p0, b1, acc[0][1]);
            acc[1][0] = fma2(p1, b0, acc[1][0]); acc[1][1] = fma2(p1, b1, acc[1][1]);
            acc[2][0] = fma2(p2, b0, acc[2][0]); acc[2][1] = fma2(p2, b1, acc[2][1]);
            acc[3][0] = fma2(p3, b0, acc[3][0]); acc[3][1] = fma2(p3, b1, acc[3][1]);
        }
        if (pf) {
            const int nx = cur ^ 1;
            As[nx][ak + 0][am] = av.x; As[nx][ak + 1][am] = av.y;
            As[nx][ak + 2][am] = av.z; As[nx][ak + 3][am] = av.w;
            Bs[nx][ak + 0][am] = bv.x; Bs[nx][ak + 1][am] = bv.y;
            Bs[nx][ak + 2][am] = bv.z; Bs[nx][ak + 3][am] = bv.w;
        }
        __syncthreads();
    }

    const int crow = row0 + (ty << 2);
    const int ccol = col0 + (tx << 2);
#pragma unroll
    for (int m = 0; m < 4; m++) {
#pragma unroll
        for (int j = 0; j < 2; j++) {
            float2 f = up2(acc[m][j]);
            int c = ccol + 2 * j;
            if (c < N)     C[(size_t)(crow + m) * ldc + c]     = f.x + bias[c];
            if (c + 1 < N) C[(size_t)(crow + m) * ldc + c + 1] = f.y + bias[c + 1];
        }
    }
}

// ---------------------------------------------------------------------------
// Launch sequence — EXACT R8 skeleton (the 950us structure), new step kernel
// ---------------------------------------------------------------------------
extern "C" void kernel_launch(void* const* d_in, const int* in_sizes, int n_in,
                              void* d_out, int out_size)
{
    const float* x     = (const float*)d_in[0];
    const float* W     = (const float*)d_in[1];
    const float* in_w  = (const float*)d_in[2];
    const float* in_b  = (const float*)d_in[3];
    const float* out_w = (const float*)d_in[4];
    const float* out_b = (const float*)d_in[5];
    float* out = (float*)d_out;

    float *E, *Hf;
    __half *Wh, *Wl, *Hh, *Hl;
    cudaGetSymbolAddress((void**)&E,  g_E);
    cudaGetSymbolAddress((void**)&Hf, g_Hf);
    cudaGetSymbolAddress((void**)&Wh, g_Wh);
    cudaGetSymbolAddress((void**)&Wl, g_Wl);
    cudaGetSymbolAddress((void**)&Hh, g_Hh);
    cudaGetSymbolAddress((void**)&Hl, g_Hl);

    cudaFuncSetAttribute(step_hmma, cudaFuncAttributeMaxDynamicSharedMemorySize,
                         SMEM_STEP);

    // W -> fp16 hi/lo split (natural layout, streaming)
    splitW<<<4096, 256>>>(W, Wh, Wl);

    // E = x @ in_w^T + in_b   [256, 1024], K = 2048
    gemm_tn_bias<<<dim3(16, 4), 256>>>(x, 2048, in_w, 2048, in_b, E, SDIM,
                                       SDIM, 2048);

    // t = 0: H = [relu(E), 0, 0]
    init_state<<<(BATCH * TOT) / 256, 256>>>(Hh, Hl);

    // t = 1..9: H_next = relu(H @ W + g_t * [E,0,0]); t=1 has K=1024
    int cur = 0;
    for (int t = 1; t < 10; t++) {
        int K      = (t == 1) ? SDIM : TOT;
        int addE   = (t % 5 == 0) ? 1 : 0;
        int writeF = (t == 9) ? 1 : 0;
        __half* Ahp = Hh + (size_t)cur * BATCH * TOT;
        __half* Alp = Hl + (size_t)cur * BATCH * TOT;
        __half* Ohp = Hh + (size_t)(1 - cur) * BATCH * TOT;
        __half* Olp = Hl + (size_t)(1 - cur) * BATCH * TOT;
        step_hmma<<<dim3(64, 4), 128, SMEM_STEP>>>(Ahp, Alp, Wh, Wl, E,
                                                   Ohp, Olp, Hf, K, addE, writeF);
        cur = 1 - cur;
    }

    // logits = O_state @ out_w^T + out_b  (O block = cols [3072, 4096))
    gemm_tn_bias<<<dim3(16, 4), 256>>>(Hf + 3072, TOT, out_w, 1024, out_b,
                                       out, 1000, 1000, 1024);
}